// round 13
// baseline (speedup 1.0000x reference)
#include <cuda_runtime.h>
#include <cuda_fp16.h>
#include <math.h>

#define NMAX 50000
#define EMAX 1600000
#define D 128
#define HW 32    // packed fp8x4 words per node row
#define T 16
#define RP 20    // 80B smem row stride (16B multiple): aligned LDS.128

__device__ unsigned g_buf8[2][2][NMAX * HW];   // [graph][ping-pong][N*32] fp8x4 words
__device__ int   g_deg[2][NMAX];
__device__ int   g_rowstart[2][NMAX + 1];
__device__ int   g_cursor[2][NMAX];
__device__ int   g_csr[2][EMAX];
__device__ float g_invdeg[2][NMAX];
__device__ float g_colsum[2 * D];

// ---- packed math helpers ----
__device__ __forceinline__ unsigned long long pack2(float lo, float hi) {
    unsigned long long r;
    asm("mov.b64 %0, {%1, %2};" : "=l"(r) : "f"(lo), "f"(hi));
    return r;
}
__device__ __forceinline__ void unpack2(unsigned long long v, float& lo, float& hi) {
    asm("mov.b64 {%0, %1}, %2;" : "=f"(lo), "=f"(hi) : "l"(v));
}
__device__ __forceinline__ unsigned long long fma2(unsigned long long a,
                                                   unsigned long long b,
                                                   unsigned long long c) {
    unsigned long long d;
    asm("fma.rn.f32x2 %0, %1, %2, %3;" : "=l"(d) : "l"(a), "l"(b), "l"(c));
    return d;
}
__device__ __forceinline__ void fp8x4_to_h2(unsigned u, __half2& a, __half2& b) {
    unsigned short h0, h1;
    asm("mov.b32 {%0, %1}, %2;" : "=h"(h0), "=h"(h1) : "r"(u));
    unsigned r0, r1;
    asm("cvt.rn.f16x2.e4m3x2 %0, %1;" : "=r"(r0) : "h"(h0));
    asm("cvt.rn.f16x2.e4m3x2 %0, %1;" : "=r"(r1) : "h"(h1));
    a = *reinterpret_cast<__half2*>(&r0);
    b = *reinterpret_cast<__half2*>(&r1);
}
__device__ __forceinline__ unsigned short f2_to_fp8x2(float lo, float hi) {
    unsigned short r;
    asm("cvt.rn.satfinite.e4m3x2.f32 %0, %1, %2;" : "=h"(r) : "f"(hi), "f"(lo));
    return r;
}

__global__ void k_init(int n) {
    int gi = blockIdx.y;
    int i = blockIdx.x * blockDim.x + threadIdx.x;
    if (i < n) g_deg[gi][i] = 0;
    if (gi == 0 && blockIdx.x == 0 && threadIdx.x < 2 * D) g_colsum[threadIdx.x] = 0.f;
}

__global__ void k_count(const int* __restrict__ d0, const int* __restrict__ d1,
                        int e0, int e1) {
    int gi = blockIdx.y;
    const int* __restrict__ dst = gi ? d1 : d0;
    int e = gi ? e1 : e0;
    int i0 = 8 * (blockIdx.x * blockDim.x + threadIdx.x);
    if (i0 + 8 <= e) {
        int4 a = *(const int4*)&dst[i0];
        int4 b = *(const int4*)&dst[i0 + 4];
        atomicAdd(&g_deg[gi][a.x], 1);
        atomicAdd(&g_deg[gi][a.y], 1);
        atomicAdd(&g_deg[gi][a.z], 1);
        atomicAdd(&g_deg[gi][a.w], 1);
        atomicAdd(&g_deg[gi][b.x], 1);
        atomicAdd(&g_deg[gi][b.y], 1);
        atomicAdd(&g_deg[gi][b.z], 1);
        atomicAdd(&g_deg[gi][b.w], 1);
    } else {
        for (int i = i0; i < e; i++) atomicAdd(&g_deg[gi][dst[i]], 1);
    }
}

__global__ void k_scan(int n) {
    int gi = blockIdx.x;
    const int* __restrict__ deg = g_deg[gi];
    int* __restrict__ rowstart = g_rowstart[gi];
    int* __restrict__ cursor = g_cursor[gi];
    float* __restrict__ invdeg = g_invdeg[gi];

    __shared__ int s_warp[32];
    __shared__ int s_carry;
    int tid = threadIdx.x;
    int lane = tid & 31;
    int wid = tid >> 5;
    if (tid == 0) s_carry = 0;
    __syncthreads();

    for (int base = 0; base < n; base += 1024) {
        int i = base + tid;
        int v = (i < n) ? deg[i] : 0;
        int s = v;
        #pragma unroll
        for (int d = 1; d < 32; d <<= 1) {
            int t = __shfl_up_sync(0xffffffffu, s, d);
            if (lane >= d) s += t;
        }
        if (lane == 31) s_warp[wid] = s;
        __syncthreads();
        if (wid == 0) {
            int w = s_warp[lane];
            #pragma unroll
            for (int d = 1; d < 32; d <<= 1) {
                int t = __shfl_up_sync(0xffffffffu, w, d);
                if (lane >= d) w += t;
            }
            s_warp[lane] = w;
        }
        __syncthreads();
        int carry = s_carry;
        int excl = carry + (wid ? s_warp[wid - 1] : 0) + s - v;
        if (i < n) {
            rowstart[i] = excl;
            cursor[i]   = excl;
            invdeg[i]   = 1.0f / fmaxf((float)v, 1.0f);
        }
        __syncthreads();
        if (tid == 0) s_carry = carry + s_warp[31];
        __syncthreads();
    }
    if (tid == 0) rowstart[n] = s_carry;
}

__global__ void k_fill(const int* __restrict__ s0, const int* __restrict__ d0,
                       const int* __restrict__ s1, const int* __restrict__ d1,
                       int e0, int e1) {
    int gi = blockIdx.y;
    const int* __restrict__ src = gi ? s1 : s0;
    const int* __restrict__ dst = gi ? d1 : d0;
    int e = gi ? e1 : e0;
    int* __restrict__ cursor = g_cursor[gi];
    int* __restrict__ csr = g_csr[gi];
    int i0 = 8 * (blockIdx.x * blockDim.x + threadIdx.x);
    if (i0 + 8 <= e) {
        int4 da = *(const int4*)&dst[i0];
        int4 db = *(const int4*)&dst[i0 + 4];
        int4 sa = *(const int4*)&src[i0];
        int4 sb = *(const int4*)&src[i0 + 4];
        int p0 = atomicAdd(&cursor[da.x], 1);
        int p1 = atomicAdd(&cursor[da.y], 1);
        int p2 = atomicAdd(&cursor[da.z], 1);
        int p3 = atomicAdd(&cursor[da.w], 1);
        int p4 = atomicAdd(&cursor[db.x], 1);
        int p5 = atomicAdd(&cursor[db.y], 1);
        int p6 = atomicAdd(&cursor[db.z], 1);
        int p7 = atomicAdd(&cursor[db.w], 1);
        csr[p0] = sa.x;
        csr[p1] = sa.y;
        csr[p2] = sa.z;
        csr[p3] = sa.w;
        csr[p4] = sb.x;
        csr[p5] = sb.y;
        csr[p6] = sb.z;
        csr[p7] = sb.w;
    } else {
        for (int i = i0; i < e; i++) {
            int p = atomicAdd(&cursor[dst[i]], 1);
            csr[p] = src[i];
        }
    }
}

__global__ void k_feat2h(const float* __restrict__ f0, const float* __restrict__ f1, int n) {
    int gi = blockIdx.y;
    const float4* __restrict__ f = (const float4*)(gi ? f1 : f0);
    int i = blockIdx.x * blockDim.x + threadIdx.x;
    if (i < n * HW) {
        float4 v = f[i];
        unsigned short lo = f2_to_fp8x2(v.x, v.y);
        unsigned short hi = f2_to_fp8x2(v.z, v.w);
        g_buf8[gi][0][i] = (unsigned)lo | ((unsigned)hi << 16);
    }
}

// fused aggregate (mean, fp8 gathers, MLP=8) + register-blocked GEMM + bias.
// T=16 nodes/block, 128 threads.
// Agg (R11-proven): warp g -> nodes base+4g..+4g+3; lane covers cols [4*lane,4*lane+4).
// GEMM: thread = (jf = tid&31 -> features 4jf..4jf+3) x (ng = tid>>5 -> nodes 4ng..4ng+3).
//   per k: 1 LDG.128 (W) + 1 LDS.128 (rows, warp-uniform broadcast) + 8 fma2.
__global__ void __launch_bounds__(128, 8) k_layer(
    int sel_in, int sel_out,
    const float* __restrict__ W, const float* __restrict__ bias, int n, int last_layer)
{
    int gi = blockIdx.y;
    const unsigned* __restrict__ h_in = g_buf8[gi][sel_in];
    unsigned* __restrict__ h_out = g_buf8[gi][sel_out];
    const int* __restrict__ rowstart = g_rowstart[gi];
    const int* __restrict__ csr = g_csr[gi];
    const float* __restrict__ invdeg = g_invdeg[gi];

    __shared__ float rows[D][RP];
    int tid = threadIdx.x;
    int lane = tid & 31;
    int g    = tid >> 5;
    int base = blockIdx.x * T;

    // ---- aggregation (unchanged from R11) ----
    #pragma unroll
    for (int t = 0; t < 4; t++) {
        int node = base + 4 * g + t;
        float r0 = 0.f, r1 = 0.f, r2 = 0.f, r3 = 0.f;
        if (node < n) {
            int s = rowstart[node];
            int e = rowstart[node + 1];
            __half2 z = __float2half2_rn(0.f);
            __half2 aA = z, aB = z, bA = z, bB = z;
            int i = s;
            for (; i + 8 <= e; i += 8) {
                int c0 = csr[i],     c1 = csr[i + 1], c2 = csr[i + 2], c3 = csr[i + 3];
                int c4 = csr[i + 4], c5 = csr[i + 5], c6 = csr[i + 6], c7 = csr[i + 7];
                unsigned u0 = __ldcg(&h_in[(size_t)c0 * HW + lane]);
                unsigned u1 = __ldcg(&h_in[(size_t)c1 * HW + lane]);
                unsigned u2 = __ldcg(&h_in[(size_t)c2 * HW + lane]);
                unsigned u3 = __ldcg(&h_in[(size_t)c3 * HW + lane]);
                unsigned u4 = __ldcg(&h_in[(size_t)c4 * HW + lane]);
                unsigned u5 = __ldcg(&h_in[(size_t)c5 * HW + lane]);
                unsigned u6 = __ldcg(&h_in[(size_t)c6 * HW + lane]);
                unsigned u7 = __ldcg(&h_in[(size_t)c7 * HW + lane]);
                __half2 p0a, p0b, p1a, p1b, p2a, p2b, p3a, p3b;
                fp8x4_to_h2(u0, p0a, p0b);
                fp8x4_to_h2(u1, p1a, p1b);
                fp8x4_to_h2(u2, p2a, p2b);
                fp8x4_to_h2(u3, p3a, p3b);
                aA = __hadd2(aA, p0a); aB = __hadd2(aB, p0b);
                bA = __hadd2(bA, p1a); bB = __hadd2(bB, p1b);
                aA = __hadd2(aA, p2a); aB = __hadd2(aB, p2b);
                bA = __hadd2(bA, p3a); bB = __hadd2(bB, p3b);
                fp8x4_to_h2(u4, p0a, p0b);
                fp8x4_to_h2(u5, p1a, p1b);
                fp8x4_to_h2(u6, p2a, p2b);
                fp8x4_to_h2(u7, p3a, p3b);
                aA = __hadd2(aA, p0a); aB = __hadd2(aB, p0b);
                bA = __hadd2(bA, p1a); bB = __hadd2(bB, p1b);
                aA = __hadd2(aA, p2a); aB = __hadd2(aB, p2b);
                bA = __hadd2(bA, p3a); bB = __hadd2(bB, p3b);
            }
            for (; i < e; i++) {
                unsigned u = __ldcg(&h_in[(size_t)csr[i] * HW + lane]);
                __half2 pa, pb;
                fp8x4_to_h2(u, pa, pb);
                aA = __hadd2(aA, pa);
                aB = __hadd2(aB, pb);
            }
            float2 fA = __half22float2(__hadd2(aA, bA));
            float2 fB = __half22float2(__hadd2(aB, bB));
            float id = invdeg[node];
            r0 = fA.x * id;
            r1 = fA.y * id;
            r2 = fB.x * id;
            r3 = fB.y * id;
        }
        int tt = 4 * g + t;
        rows[4 * lane + 0][tt] = r0;
        rows[4 * lane + 1][tt] = r1;
        rows[4 * lane + 2][tt] = r2;
        rows[4 * lane + 3][tt] = r3;
    }
    __syncthreads();

    // ---- GEMM: features [4jf,4jf+4) x nodes [4ng,4ng+4) ----
    int jf = lane;       // feature group
    int ng = g;          // node group
    float4 bv = *(const float4*)&bias[4 * jf];
    unsigned long long a00 = pack2(bv.x, bv.x), a01 = a00;  // feat0, node pairs (0,1),(2,3)
    unsigned long long a10 = pack2(bv.y, bv.y), a11 = a10;
    unsigned long long a20 = pack2(bv.z, bv.z), a21 = a20;
    unsigned long long a30 = pack2(bv.w, bv.w), a31 = a30;

    const float4* __restrict__ W4 = (const float4*)W;
    #pragma unroll 4
    for (int k = 0; k < D; k++) {
        float4 wv = W4[k * (D / 4) + jf];
        unsigned long long w0 = pack2(wv.x, wv.x);
        unsigned long long w1 = pack2(wv.y, wv.y);
        unsigned long long w2 = pack2(wv.z, wv.z);
        unsigned long long w3 = pack2(wv.w, wv.w);
        ulonglong2 r = *(const ulonglong2*)&rows[k][4 * ng];   // broadcast within warp
        a00 = fma2(r.x, w0, a00); a01 = fma2(r.y, w0, a01);
        a10 = fma2(r.x, w1, a10); a11 = fma2(r.y, w1, a11);
        a20 = fma2(r.x, w2, a20); a21 = fma2(r.y, w2, a21);
        a30 = fma2(r.x, w3, a30); a31 = fma2(r.y, w3, a31);
    }

    float o[4][4];
    unpack2(a00, o[0][0], o[0][1]); unpack2(a01, o[0][2], o[0][3]);
    unpack2(a10, o[1][0], o[1][1]); unpack2(a11, o[1][2], o[1][3]);
    unpack2(a20, o[2][0], o[2][1]); unpack2(a21, o[2][2], o[2][3]);
    unpack2(a30, o[3][0], o[3][1]); unpack2(a31, o[3][2], o[3][3]);

    if (last_layer) {
        float c0 = 0.f, c1 = 0.f, c2 = 0.f, c3 = 0.f;
        #pragma unroll
        for (int t = 0; t < 4; t++) {
            if (base + 4 * ng + t < n) {
                c0 += o[0][t];
                c1 += o[1][t];
                c2 += o[2][t];
                c3 += o[3][t];
            }
        }
        atomicAdd(&g_colsum[gi * D + 4 * jf + 0], c0);
        atomicAdd(&g_colsum[gi * D + 4 * jf + 1], c1);
        atomicAdd(&g_colsum[gi * D + 4 * jf + 2], c2);
        atomicAdd(&g_colsum[gi * D + 4 * jf + 3], c3);
    } else {
        // 4 consecutive features -> one fp8x4 word per node, no shuffles
        #pragma unroll
        for (int t = 0; t < 4; t++) {
            int node = base + 4 * ng + t;
            if (node < n) {
                unsigned short lo = f2_to_fp8x2(o[0][t], o[1][t]);
                unsigned short hi = f2_to_fp8x2(o[2][t], o[3][t]);
                h_out[(size_t)node * HW + jf] = (unsigned)lo | ((unsigned)hi << 16);
            }
        }
    }
}

__global__ void k_match(const float* __restrict__ Wr,  const float* __restrict__ br,
                        const float* __restrict__ Wm1, const float* __restrict__ bm1,
                        const float* __restrict__ Wm2, const float* __restrict__ bm2,
                        float n_nodes, float* __restrict__ out)
{
    __shared__ float c[2 * D];
    __shared__ float red[D];
    int tid = threadIdx.x;
    int g = tid / D;
    int j = tid % D;
    float invn = 1.0f / n_nodes;

    float acc = br[j];
    for (int k = 0; k < D; k++)
        acc += (g_colsum[g * D + k] * invn) * Wr[k * D + j];
    c[tid] = 1.0f / (1.0f + expf(-acc));
    __syncthreads();

    if (tid < D) {
        float d1 = bm1[tid];
        for (int i = 0; i < 2 * D; i++)
            d1 += c[i] * Wm1[i * D + tid];
        red[tid] = d1 * Wm2[tid];
    }
    __syncthreads();

    if (tid == 0) {
        float s = 0.f;
        for (int i = 0; i < D; i++) s += red[i];
        out[0] = 1.0f / (1.0f + expf(-(s + bm2[0])));
    }
}

extern "C" void kernel_launch(void* const* d_in, const int* in_sizes, int n_in,
                              void* d_out, int out_size)
{
    const float* feat_p = (const float*)d_in[0];
    const int*   src_p  = (const int*)d_in[1];
    const int*   dst_p  = (const int*)d_in[2];
    const float* feat_s = (const float*)d_in[3];
    const int*   src_s  = (const int*)d_in[4];
    const int*   dst_s  = (const int*)d_in[5];
    const float* W[3]   = { (const float*)d_in[6], (const float*)d_in[8], (const float*)d_in[10] };
    const float* b[3]   = { (const float*)d_in[7], (const float*)d_in[9], (const float*)d_in[11] };
    const float* Wr  = (const float*)d_in[12];
    const float* br  = (const float*)d_in[13];
    const float* Wm1 = (const float*)d_in[14];
    const float* bm1 = (const float*)d_in[15];
    const float* Wm2 = (const float*)d_in[16];
    const float* bm2 = (const float*)d_in[17];

    int n  = in_sizes[0] / D;
    int e0 = in_sizes[1];
    int e1 = in_sizes[4];
    int emax = e0 > e1 ? e0 : e1;

    dim3 gN((n + 511) / 512, 2);
    dim3 gE8(((emax + 7) / 8 + 511) / 512, 2);
    dim3 gF((n * HW + 255) / 256, 2);

    k_init<<<gN, 512>>>(n);
    k_count<<<gE8, 512>>>(dst_p, dst_s, e0, e1);
    k_scan<<<2, 1024>>>(n);
    k_fill<<<gE8, 512>>>(src_p, dst_p, src_s, dst_s, e0, e1);
    k_feat2h<<<gF, 256>>>(feat_p, feat_s, n);

    dim3 gL((n + T - 1) / T, 2);
    k_layer<<<gL, 128>>>(0, 1, W[0], b[0], n, 0);   // feat(fp8) -> buf1
    k_layer<<<gL, 128>>>(1, 0, W[1], b[1], n, 0);   // buf1 -> buf0
    k_layer<<<gL, 128>>>(0, 1, W[2], b[2], n, 1);   // buf0 -> colsum only

    k_match<<<1, 256>>>(Wr, br, Wm1, bm1, Wm2, bm2, (float)n, (float*)d_out);
}

// round 14
// speedup vs baseline: 1.5856x; 1.5856x over previous
#include <cuda_runtime.h>
#include <cuda_fp16.h>
#include <math.h>

#define NMAX 50000
#define EMAX 1600000
#define D 128
#define HW 32    // packed fp8x4 words per node row
#define T 16
#define RP 20    // 80B smem row stride: aligned ulonglong2 LDS.128

__device__ unsigned g_buf8[2][2][NMAX * HW];   // [graph][ping-pong][N*32] fp8x4 words
__device__ int   g_deg[2][NMAX];
__device__ int   g_rowstart[2][NMAX + 1];
__device__ int   g_cursor[2][NMAX];
__device__ int   g_csr[2][EMAX];
__device__ float g_invdeg[2][NMAX];
__device__ float g_colsum[2 * D];

// ---- packed math helpers ----
__device__ __forceinline__ unsigned long long pack2(float lo, float hi) {
    unsigned long long r;
    asm("mov.b64 %0, {%1, %2};" : "=l"(r) : "f"(lo), "f"(hi));
    return r;
}
__device__ __forceinline__ void unpack2(unsigned long long v, float& lo, float& hi) {
    asm("mov.b64 {%0, %1}, %2;" : "=f"(lo), "=f"(hi) : "l"(v));
}
__device__ __forceinline__ unsigned long long fma2(unsigned long long a,
                                                   unsigned long long b,
                                                   unsigned long long c) {
    unsigned long long d;
    asm("fma.rn.f32x2 %0, %1, %2, %3;" : "=l"(d) : "l"(a), "l"(b), "l"(c));
    return d;
}
__device__ __forceinline__ void fp8x4_to_h2(unsigned u, __half2& a, __half2& b) {
    unsigned short h0, h1;
    asm("mov.b32 {%0, %1}, %2;" : "=h"(h0), "=h"(h1) : "r"(u));
    unsigned r0, r1;
    asm("cvt.rn.f16x2.e4m3x2 %0, %1;" : "=r"(r0) : "h"(h0));
    asm("cvt.rn.f16x2.e4m3x2 %0, %1;" : "=r"(r1) : "h"(h1));
    a = *reinterpret_cast<__half2*>(&r0);
    b = *reinterpret_cast<__half2*>(&r1);
}
__device__ __forceinline__ unsigned short f2_to_fp8x2(float lo, float hi) {
    unsigned short r;
    asm("cvt.rn.satfinite.e4m3x2.f32 %0, %1, %2;" : "=h"(r) : "f"(hi), "f"(lo));
    return r;
}

__global__ void k_init(int n) {
    int gi = blockIdx.y;
    int i = blockIdx.x * blockDim.x + threadIdx.x;
    if (i < n) g_deg[gi][i] = 0;
    if (gi == 0 && blockIdx.x == 0 && threadIdx.x < 2 * D) g_colsum[threadIdx.x] = 0.f;
}

__global__ void k_count(const int* __restrict__ d0, const int* __restrict__ d1,
                        int e0, int e1) {
    int gi = blockIdx.y;
    const int* __restrict__ dst = gi ? d1 : d0;
    int e = gi ? e1 : e0;
    int i0 = 8 * (blockIdx.x * blockDim.x + threadIdx.x);
    if (i0 + 8 <= e) {
        int4 a = *(const int4*)&dst[i0];
        int4 b = *(const int4*)&dst[i0 + 4];
        atomicAdd(&g_deg[gi][a.x], 1);
        atomicAdd(&g_deg[gi][a.y], 1);
        atomicAdd(&g_deg[gi][a.z], 1);
        atomicAdd(&g_deg[gi][a.w], 1);
        atomicAdd(&g_deg[gi][b.x], 1);
        atomicAdd(&g_deg[gi][b.y], 1);
        atomicAdd(&g_deg[gi][b.z], 1);
        atomicAdd(&g_deg[gi][b.w], 1);
    } else {
        for (int i = i0; i < e; i++) atomicAdd(&g_deg[gi][dst[i]], 1);
    }
}

__global__ void k_scan(int n) {
    int gi = blockIdx.x;
    const int* __restrict__ deg = g_deg[gi];
    int* __restrict__ rowstart = g_rowstart[gi];
    int* __restrict__ cursor = g_cursor[gi];
    float* __restrict__ invdeg = g_invdeg[gi];

    __shared__ int s_warp[32];
    __shared__ int s_carry;
    int tid = threadIdx.x;
    int lane = tid & 31;
    int wid = tid >> 5;
    if (tid == 0) s_carry = 0;
    __syncthreads();

    for (int base = 0; base < n; base += 1024) {
        int i = base + tid;
        int v = (i < n) ? deg[i] : 0;
        int s = v;
        #pragma unroll
        for (int d = 1; d < 32; d <<= 1) {
            int t = __shfl_up_sync(0xffffffffu, s, d);
            if (lane >= d) s += t;
        }
        if (lane == 31) s_warp[wid] = s;
        __syncthreads();
        if (wid == 0) {
            int w = s_warp[lane];
            #pragma unroll
            for (int d = 1; d < 32; d <<= 1) {
                int t = __shfl_up_sync(0xffffffffu, w, d);
                if (lane >= d) w += t;
            }
            s_warp[lane] = w;
        }
        __syncthreads();
        int carry = s_carry;
        int excl = carry + (wid ? s_warp[wid - 1] : 0) + s - v;
        if (i < n) {
            rowstart[i] = excl;
            cursor[i]   = excl;
            invdeg[i]   = 1.0f / fmaxf((float)v, 1.0f);
        }
        __syncthreads();
        if (tid == 0) s_carry = carry + s_warp[31];
        __syncthreads();
    }
    if (tid == 0) rowstart[n] = s_carry;
}

__global__ void k_fill(const int* __restrict__ s0, const int* __restrict__ d0,
                       const int* __restrict__ s1, const int* __restrict__ d1,
                       int e0, int e1) {
    int gi = blockIdx.y;
    const int* __restrict__ src = gi ? s1 : s0;
    const int* __restrict__ dst = gi ? d1 : d0;
    int e = gi ? e1 : e0;
    int* __restrict__ cursor = g_cursor[gi];
    int* __restrict__ csr = g_csr[gi];
    int i0 = 8 * (blockIdx.x * blockDim.x + threadIdx.x);
    if (i0 + 8 <= e) {
        int4 da = *(const int4*)&dst[i0];
        int4 db = *(const int4*)&dst[i0 + 4];
        int4 sa = *(const int4*)&src[i0];
        int4 sb = *(const int4*)&src[i0 + 4];
        int p0 = atomicAdd(&cursor[da.x], 1);
        int p1 = atomicAdd(&cursor[da.y], 1);
        int p2 = atomicAdd(&cursor[da.z], 1);
        int p3 = atomicAdd(&cursor[da.w], 1);
        int p4 = atomicAdd(&cursor[db.x], 1);
        int p5 = atomicAdd(&cursor[db.y], 1);
        int p6 = atomicAdd(&cursor[db.z], 1);
        int p7 = atomicAdd(&cursor[db.w], 1);
        csr[p0] = sa.x;
        csr[p1] = sa.y;
        csr[p2] = sa.z;
        csr[p3] = sa.w;
        csr[p4] = sb.x;
        csr[p5] = sb.y;
        csr[p6] = sb.z;
        csr[p7] = sb.w;
    } else {
        for (int i = i0; i < e; i++) {
            int p = atomicAdd(&cursor[dst[i]], 1);
            csr[p] = src[i];
        }
    }
}

__global__ void k_feat2h(const float* __restrict__ f0, const float* __restrict__ f1, int n) {
    int gi = blockIdx.y;
    const float4* __restrict__ f = (const float4*)(gi ? f1 : f0);
    int i = blockIdx.x * blockDim.x + threadIdx.x;
    if (i < n * HW) {
        float4 v = f[i];
        unsigned short lo = f2_to_fp8x2(v.x, v.y);
        unsigned short hi = f2_to_fp8x2(v.z, v.w);
        g_buf8[gi][0][i] = (unsigned)lo | ((unsigned)hi << 16);
    }
}

// fused aggregate (mean, fp8 gathers, lane-cooperative index fetch) + GEMM + bias.
// T=16 nodes/block, 128 threads. Agg: warp g -> nodes base+4g..+4g+3; lane covers
// cols [4*lane,4*lane+4). Indices: 1 LDG per 32 edges + shfl broadcast (no uniform
// LDG chain per iteration). GEMM: exact R11 structure (thread = out feature).
__global__ void __launch_bounds__(128, 8) k_layer(
    int sel_in, int sel_out,
    const float* __restrict__ W, const float* __restrict__ bias, int n, int last_layer)
{
    int gi = blockIdx.y;
    const unsigned* __restrict__ h_in = g_buf8[gi][sel_in];
    unsigned* __restrict__ h_out = g_buf8[gi][sel_out];
    const int* __restrict__ rowstart = g_rowstart[gi];
    const int* __restrict__ csr = g_csr[gi];
    const float* __restrict__ invdeg = g_invdeg[gi];

    __shared__ float rows[D][RP];
    int tid = threadIdx.x;
    int lane = tid & 31;
    int g    = tid >> 5;
    int base = blockIdx.x * T;

    #pragma unroll
    for (int t = 0; t < 4; t++) {
        int node = base + 4 * g + t;
        float r0 = 0.f, r1 = 0.f, r2 = 0.f, r3 = 0.f;
        if (node < n) {
            int s = rowstart[node];
            int e = rowstart[node + 1];
            __half2 z = __float2half2_rn(0.f);
            __half2 aA = z, aB = z, bA = z, bB = z;

            for (int i = s; i < e; i += 32) {
                // lane-cooperative index fetch: 1 LDG for up to 32 edges
                int pos = i + lane;
                int myidx = csr[pos < e ? pos : (e - 1)];
                int cnt = e - i;
                if (cnt > 32) cnt = 32;
                int j = 0;
                for (; j + 8 <= cnt; j += 8) {
                    int c0 = __shfl_sync(0xffffffffu, myidx, j + 0);
                    int c1 = __shfl_sync(0xffffffffu, myidx, j + 1);
                    int c2 = __shfl_sync(0xffffffffu, myidx, j + 2);
                    int c3 = __shfl_sync(0xffffffffu, myidx, j + 3);
                    int c4 = __shfl_sync(0xffffffffu, myidx, j + 4);
                    int c5 = __shfl_sync(0xffffffffu, myidx, j + 5);
                    int c6 = __shfl_sync(0xffffffffu, myidx, j + 6);
                    int c7 = __shfl_sync(0xffffffffu, myidx, j + 7);
                    unsigned u0 = __ldcg(&h_in[(size_t)c0 * HW + lane]);
                    unsigned u1 = __ldcg(&h_in[(size_t)c1 * HW + lane]);
                    unsigned u2 = __ldcg(&h_in[(size_t)c2 * HW + lane]);
                    unsigned u3 = __ldcg(&h_in[(size_t)c3 * HW + lane]);
                    unsigned u4 = __ldcg(&h_in[(size_t)c4 * HW + lane]);
                    unsigned u5 = __ldcg(&h_in[(size_t)c5 * HW + lane]);
                    unsigned u6 = __ldcg(&h_in[(size_t)c6 * HW + lane]);
                    unsigned u7 = __ldcg(&h_in[(size_t)c7 * HW + lane]);
                    __half2 p0a, p0b, p1a, p1b, p2a, p2b, p3a, p3b;
                    fp8x4_to_h2(u0, p0a, p0b);
                    fp8x4_to_h2(u1, p1a, p1b);
                    fp8x4_to_h2(u2, p2a, p2b);
                    fp8x4_to_h2(u3, p3a, p3b);
                    aA = __hadd2(aA, p0a); aB = __hadd2(aB, p0b);
                    bA = __hadd2(bA, p1a); bB = __hadd2(bB, p1b);
                    aA = __hadd2(aA, p2a); aB = __hadd2(aB, p2b);
                    bA = __hadd2(bA, p3a); bB = __hadd2(bB, p3b);
                    fp8x4_to_h2(u4, p0a, p0b);
                    fp8x4_to_h2(u5, p1a, p1b);
                    fp8x4_to_h2(u6, p2a, p2b);
                    fp8x4_to_h2(u7, p3a, p3b);
                    aA = __hadd2(aA, p0a); aB = __hadd2(aB, p0b);
                    bA = __hadd2(bA, p1a); bB = __hadd2(bB, p1b);
                    aA = __hadd2(aA, p2a); aB = __hadd2(aB, p2b);
                    bA = __hadd2(bA, p3a); bB = __hadd2(bB, p3b);
                }
                for (; j < cnt; j++) {
                    int c = __shfl_sync(0xffffffffu, myidx, j);
                    unsigned u = __ldcg(&h_in[(size_t)c * HW + lane]);
                    __half2 pa, pb;
                    fp8x4_to_h2(u, pa, pb);
                    aA = __hadd2(aA, pa);
                    aB = __hadd2(aB, pb);
                }
            }
            float2 fA = __half22float2(__hadd2(aA, bA));
            float2 fB = __half22float2(__hadd2(aB, bB));
            float id = invdeg[node];
            r0 = fA.x * id;
            r1 = fA.y * id;
            r2 = fB.x * id;
            r3 = fB.y * id;
        }
        int tt = 4 * g + t;
        rows[4 * lane + 0][tt] = r0;
        rows[4 * lane + 1][tt] = r1;
        rows[4 * lane + 2][tt] = r2;
        rows[4 * lane + 3][tt] = r3;
    }
    __syncthreads();

    // ---- GEMM (exact R11 structure): out[node][tid], 16 nodes/thread ----
    float bv = bias[tid];
    unsigned long long a0 = pack2(bv, bv);
    unsigned long long a1 = a0, a2 = a0, a3 = a0, a4 = a0, a5 = a0, a6 = a0, a7 = a0;

    #pragma unroll 4
    for (int k = 0; k < D; k++) {
        float wv = W[k * D + tid];
        unsigned long long w2 = pack2(wv, wv);
        const ulonglong2* rp = (const ulonglong2*)&rows[k][0];
        ulonglong2 rA = rp[0];
        ulonglong2 rB = rp[1];
        ulonglong2 rC = rp[2];
        ulonglong2 rD = rp[3];
        a0 = fma2(rA.x, w2, a0);
        a1 = fma2(rA.y, w2, a1);
        a2 = fma2(rB.x, w2, a2);
        a3 = fma2(rB.y, w2, a3);
        a4 = fma2(rC.x, w2, a4);
        a5 = fma2(rC.y, w2, a5);
        a6 = fma2(rD.x, w2, a6);
        a7 = fma2(rD.y, w2, a7);
    }

    float o[T];
    unpack2(a0, o[0],  o[1]);
    unpack2(a1, o[2],  o[3]);
    unpack2(a2, o[4],  o[5]);
    unpack2(a3, o[6],  o[7]);
    unpack2(a4, o[8],  o[9]);
    unpack2(a5, o[10], o[11]);
    unpack2(a6, o[12], o[13]);
    unpack2(a7, o[14], o[15]);

    if (last_layer) {
        float csum = 0.f;
        #pragma unroll
        for (int t = 0; t < T; t++)
            if (base + t < n) csum += o[t];
        atomicAdd(&g_colsum[gi * D + tid], csum);
    } else {
        // pack 4 adjacent output features into one fp8x4 word (R11 epilogue)
        #pragma unroll
        for (int t = 0; t < T; t++) {
            float nb = __shfl_xor_sync(0xffffffffu, o[t], 1);
            unsigned short pr = f2_to_fp8x2(o[t], nb);
            unsigned pr32 = pr;
            unsigned other = __shfl_xor_sync(0xffffffffu, pr32, 2);
            int node = base + t;
            if ((tid & 3) == 0 && node < n)
                h_out[(size_t)node * HW + (tid >> 2)] = pr32 | (other << 16);
        }
    }
}

__global__ void k_match(const float* __restrict__ Wr,  const float* __restrict__ br,
                        const float* __restrict__ Wm1, const float* __restrict__ bm1,
                        const float* __restrict__ Wm2, const float* __restrict__ bm2,
                        float n_nodes, float* __restrict__ out)
{
    __shared__ float c[2 * D];
    __shared__ float red[D];
    int tid = threadIdx.x;
    int g = tid / D;
    int j = tid % D;
    float invn = 1.0f / n_nodes;

    float acc = br[j];
    for (int k = 0; k < D; k++)
        acc += (g_colsum[g * D + k] * invn) * Wr[k * D + j];
    c[tid] = 1.0f / (1.0f + expf(-acc));
    __syncthreads();

    if (tid < D) {
        float d1 = bm1[tid];
        for (int i = 0; i < 2 * D; i++)
            d1 += c[i] * Wm1[i * D + tid];
        red[tid] = d1 * Wm2[tid];
    }
    __syncthreads();

    if (tid == 0) {
        float s = 0.f;
        for (int i = 0; i < D; i++) s += red[i];
        out[0] = 1.0f / (1.0f + expf(-(s + bm2[0])));
    }
}

extern "C" void kernel_launch(void* const* d_in, const int* in_sizes, int n_in,
                              void* d_out, int out_size)
{
    const float* feat_p = (const float*)d_in[0];
    const int*   src_p  = (const int*)d_in[1];
    const int*   dst_p  = (const int*)d_in[2];
    const float* feat_s = (const float*)d_in[3];
    const int*   src_s  = (const int*)d_in[4];
    const int*   dst_s  = (const int*)d_in[5];
    const float* W[3]   = { (const float*)d_in[6], (const float*)d_in[8], (const float*)d_in[10] };
    const float* b[3]   = { (const float*)d_in[7], (const float*)d_in[9], (const float*)d_in[11] };
    const float* Wr  = (const float*)d_in[12];
    const float* br  = (const float*)d_in[13];
    const float* Wm1 = (const float*)d_in[14];
    const float* bm1 = (const float*)d_in[15];
    const float* Wm2 = (const float*)d_in[16];
    const float* bm2 = (const float*)d_in[17];

    int n  = in_sizes[0] / D;
    int e0 = in_sizes[1];
    int e1 = in_sizes[4];
    int emax = e0 > e1 ? e0 : e1;

    dim3 gN((n + 511) / 512, 2);
    dim3 gE8(((emax + 7) / 8 + 511) / 512, 2);
    dim3 gF((n * HW + 255) / 256, 2);

    k_init<<<gN, 512>>>(n);
    k_count<<<gE8, 512>>>(dst_p, dst_s, e0, e1);
    k_scan<<<2, 1024>>>(n);
    k_fill<<<gE8, 512>>>(src_p, dst_p, src_s, dst_s, e0, e1);
    k_feat2h<<<gF, 256>>>(feat_p, feat_s, n);

    dim3 gL((n + T - 1) / T, 2);
    k_layer<<<gL, 128>>>(0, 1, W[0], b[0], n, 0);   // feat(fp8) -> buf1
    k_layer<<<gL, 128>>>(1, 0, W[1], b[1], n, 0);   // buf1 -> buf0
    k_layer<<<gL, 128>>>(0, 1, W[2], b[2], n, 1);   // buf0 -> colsum only

    k_match<<<1, 256>>>(Wr, br, Wm1, bm1, Wm2, bm2, (float)n, (float*)d_out);
}

// round 16
// speedup vs baseline: 1.8026x; 1.1369x over previous
#include <cuda_runtime.h>
#include <cuda_fp16.h>
#include <math.h>

#define NMAX 50000
#define EMAX 1600000
#define D 128
#define HW 32    // packed fp8x4 words per node row
#define T 16
#define RP 20    // 80B smem row stride: aligned ulonglong2 LDS.128

__device__ unsigned g_buf8[2][2][NMAX * HW];   // [graph][ping-pong][N*32] fp8x4 words
__device__ int   g_deg[2][NMAX];
__device__ int   g_rowstart[2][NMAX + 1];
__device__ int   g_cursor[2][NMAX];
__device__ int   g_csr[2][EMAX];
__device__ float g_invdeg[2][NMAX];
__device__ float g_w[2][NMAX];                 // w[src] = sum over out-edges of invdeg[dst]
__device__ float g_colsum[2 * D];              // colsum of agg3 (pre-GEMM)

// ---- packed math helpers ----
__device__ __forceinline__ unsigned long long pack2(float lo, float hi) {
    unsigned long long r;
    asm("mov.b64 %0, {%1, %2};" : "=l"(r) : "f"(lo), "f"(hi));
    return r;
}
__device__ __forceinline__ void unpack2(unsigned long long v, float& lo, float& hi) {
    asm("mov.b64 {%0, %1}, %2;" : "=f"(lo), "=f"(hi) : "l"(v));
}
__device__ __forceinline__ unsigned long long fma2(unsigned long long a,
                                                   unsigned long long b,
                                                   unsigned long long c) {
    unsigned long long d;
    asm("fma.rn.f32x2 %0, %1, %2, %3;" : "=l"(d) : "l"(a), "l"(b), "l"(c));
    return d;
}
__device__ __forceinline__ void fp8x4_to_h2(unsigned u, __half2& a, __half2& b) {
    unsigned short h0, h1;
    asm("mov.b32 {%0, %1}, %2;" : "=h"(h0), "=h"(h1) : "r"(u));
    unsigned r0, r1;
    asm("cvt.rn.f16x2.e4m3x2 %0, %1;" : "=r"(r0) : "h"(h0));
    asm("cvt.rn.f16x2.e4m3x2 %0, %1;" : "=r"(r1) : "h"(h1));
    a = *reinterpret_cast<__half2*>(&r0);
    b = *reinterpret_cast<__half2*>(&r1);
}
__device__ __forceinline__ unsigned short f2_to_fp8x2(float lo, float hi) {
    unsigned short r;
    asm("cvt.rn.satfinite.e4m3x2.f32 %0, %1, %2;" : "=h"(r) : "f"(hi), "f"(lo));
    return r;
}

__global__ void k_init(int n) {
    int gi = blockIdx.y;
    int i = blockIdx.x * blockDim.x + threadIdx.x;
    if (i < n) {
        g_deg[gi][i] = 0;
        g_w[gi][i] = 0.f;
    }
    if (gi == 0 && blockIdx.x == 0 && threadIdx.x < 2 * D) g_colsum[threadIdx.x] = 0.f;
}

__global__ void k_count(const int* __restrict__ d0, const int* __restrict__ d1,
                        int e0, int e1) {
    int gi = blockIdx.y;
    const int* __restrict__ dst = gi ? d1 : d0;
    int e = gi ? e1 : e0;
    int i0 = 8 * (blockIdx.x * blockDim.x + threadIdx.x);
    if (i0 + 8 <= e) {
        int4 a = *(const int4*)&dst[i0];
        int4 b = *(const int4*)&dst[i0 + 4];
        atomicAdd(&g_deg[gi][a.x], 1);
        atomicAdd(&g_deg[gi][a.y], 1);
        atomicAdd(&g_deg[gi][a.z], 1);
        atomicAdd(&g_deg[gi][a.w], 1);
        atomicAdd(&g_deg[gi][b.x], 1);
        atomicAdd(&g_deg[gi][b.y], 1);
        atomicAdd(&g_deg[gi][b.z], 1);
        atomicAdd(&g_deg[gi][b.w], 1);
    } else {
        for (int i = i0; i < e; i++) atomicAdd(&g_deg[gi][dst[i]], 1);
    }
}

__global__ void k_scan(int n) {
    int gi = blockIdx.x;
    const int* __restrict__ deg = g_deg[gi];
    int* __restrict__ rowstart = g_rowstart[gi];
    int* __restrict__ cursor = g_cursor[gi];
    float* __restrict__ invdeg = g_invdeg[gi];

    __shared__ int s_warp[32];
    __shared__ int s_carry;
    int tid = threadIdx.x;
    int lane = tid & 31;
    int wid = tid >> 5;
    if (tid == 0) s_carry = 0;
    __syncthreads();

    for (int base = 0; base < n; base += 1024) {
        int i = base + tid;
        int v = (i < n) ? deg[i] : 0;
        int s = v;
        #pragma unroll
        for (int d = 1; d < 32; d <<= 1) {
            int t = __shfl_up_sync(0xffffffffu, s, d);
            if (lane >= d) s += t;
        }
        if (lane == 31) s_warp[wid] = s;
        __syncthreads();
        if (wid == 0) {
            int w = s_warp[lane];
            #pragma unroll
            for (int d = 1; d < 32; d <<= 1) {
                int t = __shfl_up_sync(0xffffffffu, w, d);
                if (lane >= d) w += t;
            }
            s_warp[lane] = w;
        }
        __syncthreads();
        int carry = s_carry;
        int excl = carry + (wid ? s_warp[wid - 1] : 0) + s - v;
        if (i < n) {
            rowstart[i] = excl;
            cursor[i]   = excl;
            invdeg[i]   = 1.0f / fmaxf((float)v, 1.0f);
        }
        __syncthreads();
        if (tid == 0) s_carry = carry + s_warp[31];
        __syncthreads();
    }
    if (tid == 0) rowstart[n] = s_carry;
}

// CSR fill + fused w accumulation: w[src] += invdeg[dst] per edge
__global__ void k_fill(const int* __restrict__ s0, const int* __restrict__ d0,
                       const int* __restrict__ s1, const int* __restrict__ d1,
                       int e0, int e1) {
    int gi = blockIdx.y;
    const int* __restrict__ src = gi ? s1 : s0;
    const int* __restrict__ dst = gi ? d1 : d0;
    int e = gi ? e1 : e0;
    int* __restrict__ cursor = g_cursor[gi];
    int* __restrict__ csr = g_csr[gi];
    const float* __restrict__ invdeg = g_invdeg[gi];
    float* __restrict__ wv = g_w[gi];
    int i0 = 8 * (blockIdx.x * blockDim.x + threadIdx.x);
    if (i0 + 8 <= e) {
        int4 da = *(const int4*)&dst[i0];
        int4 db = *(const int4*)&dst[i0 + 4];
        int4 sa = *(const int4*)&src[i0];
        int4 sb = *(const int4*)&src[i0 + 4];
        int p0 = atomicAdd(&cursor[da.x], 1);
        int p1 = atomicAdd(&cursor[da.y], 1);
        int p2 = atomicAdd(&cursor[da.z], 1);
        int p3 = atomicAdd(&cursor[da.w], 1);
        int p4 = atomicAdd(&cursor[db.x], 1);
        int p5 = atomicAdd(&cursor[db.y], 1);
        int p6 = atomicAdd(&cursor[db.z], 1);
        int p7 = atomicAdd(&cursor[db.w], 1);
        csr[p0] = sa.x;
        csr[p1] = sa.y;
        csr[p2] = sa.z;
        csr[p3] = sa.w;
        csr[p4] = sb.x;
        csr[p5] = sb.y;
        csr[p6] = sb.z;
        csr[p7] = sb.w;
        // fused: w[src] += invdeg[dst] (overlaps with atomic latency above)
        atomicAdd(&wv[sa.x], invdeg[da.x]);
        atomicAdd(&wv[sa.y], invdeg[da.y]);
        atomicAdd(&wv[sa.z], invdeg[da.z]);
        atomicAdd(&wv[sa.w], invdeg[da.w]);
        atomicAdd(&wv[sb.x], invdeg[db.x]);
        atomicAdd(&wv[sb.y], invdeg[db.y]);
        atomicAdd(&wv[sb.z], invdeg[db.z]);
        atomicAdd(&wv[sb.w], invdeg[db.w]);
    } else {
        for (int i = i0; i < e; i++) {
            int d = dst[i];
            int s = src[i];
            int p = atomicAdd(&cursor[d], 1);
            csr[p] = s;
            atomicAdd(&wv[s], invdeg[d]);
        }
    }
}

__global__ void k_feat2h(const float* __restrict__ f0, const float* __restrict__ f1, int n) {
    int gi = blockIdx.y;
    const float4* __restrict__ f = (const float4*)(gi ? f1 : f0);
    int i = blockIdx.x * blockDim.x + threadIdx.x;
    if (i < n * HW) {
        float4 v = f[i];
        unsigned short lo = f2_to_fp8x2(v.x, v.y);
        unsigned short hi = f2_to_fp8x2(v.z, v.w);
        g_buf8[gi][0][i] = (unsigned)lo | ((unsigned)hi << 16);
    }
}

// fused aggregate (mean, fp8 gathers MLP=8) + GEMM (f32x2) + bias (exact R11 kernel).
__global__ void __launch_bounds__(128, 8) k_layer(
    int sel_in, int sel_out,
    const float* __restrict__ W, const float* __restrict__ bias, int n)
{
    int gi = blockIdx.y;
    const unsigned* __restrict__ h_in = g_buf8[gi][sel_in];
    unsigned* __restrict__ h_out = g_buf8[gi][sel_out];
    const int* __restrict__ rowstart = g_rowstart[gi];
    const int* __restrict__ csr = g_csr[gi];
    const float* __restrict__ invdeg = g_invdeg[gi];

    __shared__ float rows[D][RP];
    int tid = threadIdx.x;
    int lane = tid & 31;
    int g    = tid >> 5;
    int base = blockIdx.x * T;

    #pragma unroll
    for (int t = 0; t < 4; t++) {
        int node = base + 4 * g + t;
        float r0 = 0.f, r1 = 0.f, r2 = 0.f, r3 = 0.f;
        if (node < n) {
            int s = rowstart[node];
            int e = rowstart[node + 1];
            __half2 z = __float2half2_rn(0.f);
            __half2 aA = z, aB = z, bA = z, bB = z;
            int i = s;
            for (; i + 8 <= e; i += 8) {
                int c0 = csr[i],     c1 = csr[i + 1], c2 = csr[i + 2], c3 = csr[i + 3];
                int c4 = csr[i + 4], c5 = csr[i + 5], c6 = csr[i + 6], c7 = csr[i + 7];
                unsigned u0 = __ldcg(&h_in[(size_t)c0 * HW + lane]);
                unsigned u1 = __ldcg(&h_in[(size_t)c1 * HW + lane]);
                unsigned u2 = __ldcg(&h_in[(size_t)c2 * HW + lane]);
                unsigned u3 = __ldcg(&h_in[(size_t)c3 * HW + lane]);
                unsigned u4 = __ldcg(&h_in[(size_t)c4 * HW + lane]);
                unsigned u5 = __ldcg(&h_in[(size_t)c5 * HW + lane]);
                unsigned u6 = __ldcg(&h_in[(size_t)c6 * HW + lane]);
                unsigned u7 = __ldcg(&h_in[(size_t)c7 * HW + lane]);
                __half2 p0a, p0b, p1a, p1b, p2a, p2b, p3a, p3b;
                fp8x4_to_h2(u0, p0a, p0b);
                fp8x4_to_h2(u1, p1a, p1b);
                fp8x4_to_h2(u2, p2a, p2b);
                fp8x4_to_h2(u3, p3a, p3b);
                aA = __hadd2(aA, p0a); aB = __hadd2(aB, p0b);
                bA = __hadd2(bA, p1a); bB = __hadd2(bB, p1b);
                aA = __hadd2(aA, p2a); aB = __hadd2(aB, p2b);
                bA = __hadd2(bA, p3a); bB = __hadd2(bB, p3b);
                fp8x4_to_h2(u4, p0a, p0b);
                fp8x4_to_h2(u5, p1a, p1b);
                fp8x4_to_h2(u6, p2a, p2b);
                fp8x4_to_h2(u7, p3a, p3b);
                aA = __hadd2(aA, p0a); aB = __hadd2(aB, p0b);
                bA = __hadd2(bA, p1a); bB = __hadd2(bB, p1b);
                aA = __hadd2(aA, p2a); aB = __hadd2(aB, p2b);
                bA = __hadd2(bA, p3a); bB = __hadd2(bB, p3b);
            }
            for (; i < e; i++) {
                unsigned u = __ldcg(&h_in[(size_t)csr[i] * HW + lane]);
                __half2 pa, pb;
                fp8x4_to_h2(u, pa, pb);
                aA = __hadd2(aA, pa);
                aB = __hadd2(aB, pb);
            }
            float2 fA = __half22float2(__hadd2(aA, bA));
            float2 fB = __half22float2(__hadd2(aB, bB));
            float id = invdeg[node];
            r0 = fA.x * id;
            r1 = fA.y * id;
            r2 = fB.x * id;
            r3 = fB.y * id;
        }
        int tt = 4 * g + t;
        rows[4 * lane + 0][tt] = r0;
        rows[4 * lane + 1][tt] = r1;
        rows[4 * lane + 2][tt] = r2;
        rows[4 * lane + 3][tt] = r3;
    }
    __syncthreads();

    float bv = bias[tid];
    unsigned long long a0 = pack2(bv, bv);
    unsigned long long a1 = a0, a2 = a0, a3 = a0, a4 = a0, a5 = a0, a6 = a0, a7 = a0;

    #pragma unroll 4
    for (int k = 0; k < D; k++) {
        float wv = W[k * D + tid];
        unsigned long long w2 = pack2(wv, wv);
        const ulonglong2* rp = (const ulonglong2*)&rows[k][0];
        ulonglong2 rA = rp[0];
        ulonglong2 rB = rp[1];
        ulonglong2 rC = rp[2];
        ulonglong2 rD = rp[3];
        a0 = fma2(rA.x, w2, a0);
        a1 = fma2(rA.y, w2, a1);
        a2 = fma2(rB.x, w2, a2);
        a3 = fma2(rB.y, w2, a3);
        a4 = fma2(rC.x, w2, a4);
        a5 = fma2(rC.y, w2, a5);
        a6 = fma2(rD.x, w2, a6);
        a7 = fma2(rD.y, w2, a7);
    }

    float o[T];
    unpack2(a0, o[0],  o[1]);
    unpack2(a1, o[2],  o[3]);
    unpack2(a2, o[4],  o[5]);
    unpack2(a3, o[6],  o[7]);
    unpack2(a4, o[8],  o[9]);
    unpack2(a5, o[10], o[11]);
    unpack2(a6, o[12], o[13]);
    unpack2(a7, o[14], o[15]);

    #pragma unroll
    for (int t = 0; t < T; t++) {
        float nb = __shfl_xor_sync(0xffffffffu, o[t], 1);
        unsigned short pr = f2_to_fp8x2(o[t], nb);
        unsigned pr32 = pr;
        unsigned other = __shfl_xor_sync(0xffffffffu, pr32, 2);
        int node = base + t;
        if ((tid & 3) == 0 && node < n)
            h_out[(size_t)node * HW + (tid >> 2)] = pr32 | (other << 16);
    }
}

// weighted colsum of h2: colsum[gi*D + j] = sum_n w[n] * h2[n][j]
// (= colsum of agg3 by linearity). Streaming, contiguous fp8 reads.
__global__ void k_wcolsum(int n) {
    int gi = blockIdx.y;
    const unsigned* __restrict__ h2 = g_buf8[gi][0];
    const float* __restrict__ wv = g_w[gi];
    int lane = threadIdx.x & 31;
    int wr   = threadIdx.x >> 5;

    float c0 = 0.f, c1 = 0.f, c2 = 0.f, c3 = 0.f;
    for (int node = blockIdx.x * 4 + wr; node < n; node += gridDim.x * 4) {
        float wgt = wv[node];
        unsigned u = __ldcg(&h2[(size_t)node * HW + lane]);
        __half2 pa, pb;
        fp8x4_to_h2(u, pa, pb);
        float2 fa = __half22float2(pa);
        float2 fb = __half22float2(pb);
        c0 += wgt * fa.x;
        c1 += wgt * fa.y;
        c2 += wgt * fb.x;
        c3 += wgt * fb.y;
    }
    atomicAdd(&g_colsum[gi * D + 4 * lane + 0], c0);
    atomicAdd(&g_colsum[gi * D + 4 * lane + 1], c1);
    atomicAdd(&g_colsum[gi * D + 4 * lane + 2], c2);
    atomicAdd(&g_colsum[gi * D + 4 * lane + 3], c3);
}

// final: layer-3 matvec (mean(agg3) @ W2 + b2) + readout MLP + match MLP + sigmoid
__global__ void k_match(const float* __restrict__ W2,  const float* __restrict__ b2,
                        const float* __restrict__ Wr,  const float* __restrict__ br,
                        const float* __restrict__ Wm1, const float* __restrict__ bm1,
                        const float* __restrict__ Wm2, const float* __restrict__ bm2,
                        float n_nodes, float* __restrict__ out)
{
    __shared__ float m3[2 * D];   // mean over nodes of h3
    __shared__ float c[2 * D];
    __shared__ float red[D];
    int tid = threadIdx.x;        // 256 threads
    int g = tid / D;
    int j = tid % D;
    float invn = 1.0f / n_nodes;

    // layer 3 GEMM collapsed to a matvec on the mean:
    float t3 = b2[j];
    for (int k = 0; k < D; k++)
        t3 += (g_colsum[g * D + k] * invn) * W2[k * D + j];
    m3[tid] = t3;
    __syncthreads();

    float acc = br[j];
    for (int k = 0; k < D; k++)
        acc += m3[g * D + k] * Wr[k * D + j];
    c[tid] = 1.0f / (1.0f + expf(-acc));
    __syncthreads();

    if (tid < D) {
        float d1 = bm1[tid];
        for (int i = 0; i < 2 * D; i++)
            d1 += c[i] * Wm1[i * D + tid];
        red[tid] = d1 * Wm2[tid];
    }
    __syncthreads();

    if (tid == 0) {
        float s = 0.f;
        for (int i = 0; i < D; i++) s += red[i];
        out[0] = 1.0f / (1.0f + expf(-(s + bm2[0])));
    }
}

extern "C" void kernel_launch(void* const* d_in, const int* in_sizes, int n_in,
                              void* d_out, int out_size)
{
    const float* feat_p = (const float*)d_in[0];
    const int*   src_p  = (const int*)d_in[1];
    const int*   dst_p  = (const int*)d_in[2];
    const float* feat_s = (const float*)d_in[3];
    const int*   src_s  = (const int*)d_in[4];
    const int*   dst_s  = (const int*)d_in[5];
    const float* W[3]   = { (const float*)d_in[6], (const float*)d_in[8], (const float*)d_in[10] };
    const float* b[3]   = { (const float*)d_in[7], (const float*)d_in[9], (const float*)d_in[11] };
    const float* Wr  = (const float*)d_in[12];
    const float* br  = (const float*)d_in[13];
    const float* Wm1 = (const float*)d_in[14];
    const float* bm1 = (const float*)d_in[15];
    const float* Wm2 = (const float*)d_in[16];
    const float* bm2 = (const float*)d_in[17];

    int n  = in_sizes[0] / D;
    int e0 = in_sizes[1];
    int e1 = in_sizes[4];
    int emax = e0 > e1 ? e0 : e1;

    dim3 gN((n + 511) / 512, 2);
    dim3 gE8(((emax + 7) / 8 + 511) / 512, 2);
    dim3 gF((n * HW + 255) / 256, 2);

    k_init<<<gN, 512>>>(n);
    k_count<<<gE8, 512>>>(dst_p, dst_s, e0, e1);
    k_scan<<<2, 1024>>>(n);
    k_fill<<<gE8, 512>>>(src_p, dst_p, src_s, dst_s, e0, e1);
    k_feat2h<<<gF, 256>>>(feat_p, feat_s, n);

    dim3 gL((n + T - 1) / T, 2);
    k_layer<<<gL, 128>>>(0, 1, W[0], b[0], n);   // feat(fp8) -> buf1
    k_layer<<<gL, 128>>>(1, 0, W[1], b[1], n);   // buf1 -> buf0 (= h2)

    dim3 gC(128, 2);
    k_wcolsum<<<gC, 128>>>(n);                   // colsum of agg3 via w-weighted h2 sum

    k_match<<<1, 256>>>(W[2], b[2], Wr, br, Wm1, bm1, Wm2, bm2, (float)n, (float*)d_out);
}

// round 17
// speedup vs baseline: 4.6778x; 2.5950x over previous
#include <cuda_runtime.h>
#include <math.h>

#define NMAX 50000
#define D 128

__device__ int   g_deg[2][NMAX];
__device__ float g_invdeg[2][NMAX];
__device__ float g_t[2][NMAX];     // scatter-source values: t[d] = invdeg[d] * u_prev[d]
__device__ float g_u[2][NMAX];     // current accumulation target
__device__ float g_S[2][2];        // [graph][0] = sum(u1), [1] = sum(u2)
__device__ float g_colv[2 * D];    // weighted colsum of feat with u3

// ---------------- init: zero deg, colv, S ----------------
__global__ void k_init(int n) {
    int gi = blockIdx.y;
    int i = blockIdx.x * blockDim.x + threadIdx.x;
    if (i < n) g_deg[gi][i] = 0;
    if (blockIdx.x == 0 && threadIdx.x < D) g_colv[gi * D + threadIdx.x] = 0.f;
    if (blockIdx.x == 0 && threadIdx.x < 2) g_S[gi][threadIdx.x] = 0.f;
}

// ---------------- degree count (8 edges/thread) ----------------
__global__ void k_count(const int* __restrict__ d0, const int* __restrict__ d1,
                        int e0, int e1) {
    int gi = blockIdx.y;
    const int* __restrict__ dst = gi ? d1 : d0;
    int e = gi ? e1 : e0;
    int i0 = 8 * (blockIdx.x * blockDim.x + threadIdx.x);
    if (i0 + 8 <= e) {
        int4 a = *(const int4*)&dst[i0];
        int4 b = *(const int4*)&dst[i0 + 4];
        atomicAdd(&g_deg[gi][a.x], 1);
        atomicAdd(&g_deg[gi][a.y], 1);
        atomicAdd(&g_deg[gi][a.z], 1);
        atomicAdd(&g_deg[gi][a.w], 1);
        atomicAdd(&g_deg[gi][b.x], 1);
        atomicAdd(&g_deg[gi][b.y], 1);
        atomicAdd(&g_deg[gi][b.z], 1);
        atomicAdd(&g_deg[gi][b.w], 1);
    } else {
        for (int i = i0; i < e; i++) atomicAdd(&g_deg[gi][dst[i]], 1);
    }
}

// ---------------- prep0: invdeg, t = invdeg, u = 0 ----------------
__global__ void k_prep0(int n) {
    int gi = blockIdx.y;
    int i = blockIdx.x * blockDim.x + threadIdx.x;
    if (i < n) {
        float id = 1.0f / fmaxf((float)g_deg[gi][i], 1.0f);
        g_invdeg[gi][i] = id;
        g_t[gi][i] = id;
        g_u[gi][i] = 0.f;
    }
}

// ---------------- u-pass: u[src] += t[dst] (8 edges/thread, MLP 8) ----------------
__global__ void k_upass(const int* __restrict__ s0, const int* __restrict__ d0,
                        const int* __restrict__ s1, const int* __restrict__ d1,
                        int e0, int e1) {
    int gi = blockIdx.y;
    const int* __restrict__ src = gi ? s1 : s0;
    const int* __restrict__ dst = gi ? d1 : d0;
    int e = gi ? e1 : e0;
    const float* __restrict__ t = g_t[gi];
    float* __restrict__ u = g_u[gi];
    int i0 = 8 * (blockIdx.x * blockDim.x + threadIdx.x);
    if (i0 + 8 <= e) {
        int4 da = *(const int4*)&dst[i0];
        int4 db = *(const int4*)&dst[i0 + 4];
        int4 sa = *(const int4*)&src[i0];
        int4 sb = *(const int4*)&src[i0 + 4];
        float t0 = __ldcg(&t[da.x]);
        float t1 = __ldcg(&t[da.y]);
        float t2 = __ldcg(&t[da.z]);
        float t3 = __ldcg(&t[da.w]);
        float t4 = __ldcg(&t[db.x]);
        float t5 = __ldcg(&t[db.y]);
        float t6 = __ldcg(&t[db.z]);
        float t7 = __ldcg(&t[db.w]);
        atomicAdd(&u[sa.x], t0);
        atomicAdd(&u[sa.y], t1);
        atomicAdd(&u[sa.z], t2);
        atomicAdd(&u[sa.w], t3);
        atomicAdd(&u[sb.x], t4);
        atomicAdd(&u[sb.y], t5);
        atomicAdd(&u[sb.z], t6);
        atomicAdd(&u[sb.w], t7);
    } else {
        for (int i = i0; i < e; i++)
            atomicAdd(&u[src[i]], t[dst[i]]);
    }
}

// ---------------- prep: S[lvl] += sum(u); t = invdeg*u; u = 0 ----------------
__global__ void k_prep(int n, int lvl) {
    int gi = blockIdx.y;
    int i = blockIdx.x * blockDim.x + threadIdx.x;
    float uv = 0.f;
    if (i < n) {
        uv = g_u[gi][i];
        g_t[gi][i] = g_invdeg[gi][i] * uv;
        g_u[gi][i] = 0.f;
    }
    // warp reduce for S
    #pragma unroll
    for (int m = 16; m; m >>= 1)
        uv += __shfl_xor_sync(0xffffffffu, uv, m);
    if ((threadIdx.x & 31) == 0 && uv != 0.f)
        atomicAdd(&g_S[gi][lvl], uv);
}

// ---------------- weighted colsum of feat: colv[j] = sum_n u3[n]*feat[n][j] ----------------
__global__ void k_wcol(const float* __restrict__ f0, const float* __restrict__ f1, int n) {
    int gi = blockIdx.y;
    const float* __restrict__ feat = gi ? f1 : f0;
    const float* __restrict__ u = g_u[gi];
    int j = threadIdx.x;   // 128 threads = feature column
    float acc = 0.f;
    for (int node = blockIdx.x; node < n; node += gridDim.x) {
        float w = u[node];                      // broadcast
        acc += w * feat[(size_t)node * D + j];  // coalesced
    }
    atomicAdd(&g_colv[gi * D + j], acc);
}

// ---------------- final: 3 collapsed matvecs + readout + match + sigmoid ----------------
__global__ void k_match(const float* __restrict__ W0, const float* __restrict__ b0,
                        const float* __restrict__ W1, const float* __restrict__ b1,
                        const float* __restrict__ W2, const float* __restrict__ b2,
                        const float* __restrict__ Wr, const float* __restrict__ br,
                        const float* __restrict__ Wm1, const float* __restrict__ bm1,
                        const float* __restrict__ Wm2, const float* __restrict__ bm2,
                        float n_nodes, float* __restrict__ out)
{
    __shared__ float v[2][D], c1[2][D], c2[2][D], m3[2][D];
    __shared__ float cc[2 * D];
    __shared__ float red[D];
    int tid = threadIdx.x;        // 256 threads
    int g = tid >> 7;
    int j = tid & 127;
    float invn = 1.0f / n_nodes;

    v[g][j] = g_colv[g * D + j];           // = sum u3 * feat
    __syncthreads();

    float S1 = g_S[g][0];                   // sum(u1)
    float S2 = g_S[g][1];                   // sum(u2)

    // c1 = (sum u2 * agg1)@W0 + S2*b0  = sum u2 * h1
    float a = S2 * b0[j];
    for (int k = 0; k < D; k++) a += v[g][k] * W0[k * D + j];
    c1[g][j] = a;
    __syncthreads();

    // c2 = c1@W1 + S1*b1 = sum u1 * h2
    a = S1 * b1[j];
    for (int k = 0; k < D; k++) a += c1[g][k] * W1[k * D + j];
    c2[g][j] = a;
    __syncthreads();

    // c3 = c2@W2 + N*b2 = colsum(h3);  m = mean(h3)
    a = n_nodes * b2[j];
    for (int k = 0; k < D; k++) a += c2[g][k] * W2[k * D + j];
    m3[g][j] = a * invn;
    __syncthreads();

    // readout: g_feat = sigmoid(m @ Wr + br)
    a = br[j];
    for (int k = 0; k < D; k++) a += m3[g][k] * Wr[k * D + j];
    cc[g * D + j] = 1.0f / (1.0f + expf(-a));
    __syncthreads();

    // match head
    if (tid < D) {
        float d1 = bm1[tid];
        for (int i = 0; i < 2 * D; i++)
            d1 += cc[i] * Wm1[i * D + tid];
        red[tid] = d1 * Wm2[tid];
    }
    __syncthreads();

    if (tid == 0) {
        float s = 0.f;
        for (int i = 0; i < D; i++) s += red[i];
        out[0] = 1.0f / (1.0f + expf(-(s + bm2[0])));
    }
}

// ---------------- launch ----------------
extern "C" void kernel_launch(void* const* d_in, const int* in_sizes, int n_in,
                              void* d_out, int out_size)
{
    const float* feat_p = (const float*)d_in[0];
    const int*   src_p  = (const int*)d_in[1];
    const int*   dst_p  = (const int*)d_in[2];
    const float* feat_s = (const float*)d_in[3];
    const int*   src_s  = (const int*)d_in[4];
    const int*   dst_s  = (const int*)d_in[5];
    const float* W0 = (const float*)d_in[6];
    const float* b0 = (const float*)d_in[7];
    const float* W1 = (const float*)d_in[8];
    const float* b1 = (const float*)d_in[9];
    const float* W2 = (const float*)d_in[10];
    const float* b2 = (const float*)d_in[11];
    const float* Wr  = (const float*)d_in[12];
    const float* br  = (const float*)d_in[13];
    const float* Wm1 = (const float*)d_in[14];
    const float* bm1 = (const float*)d_in[15];
    const float* Wm2 = (const float*)d_in[16];
    const float* bm2 = (const float*)d_in[17];

    int n  = in_sizes[0] / D;
    int e0 = in_sizes[1];
    int e1 = in_sizes[4];
    int emax = e0 > e1 ? e0 : e1;

    dim3 gN((n + 511) / 512, 2);
    dim3 gE8(((emax + 7) / 8 + 511) / 512, 2);
    dim3 gW(256, 2);

    k_init<<<gN, 512>>>(n);
    k_count<<<gE8, 512>>>(dst_p, dst_s, e0, e1);
    k_prep0<<<gN, 512>>>(n);

    k_upass<<<gE8, 512>>>(src_p, dst_p, src_s, dst_s, e0, e1);   // u1
    k_prep<<<gN, 512>>>(n, 0);                                   // S1, t=invdeg*u1
    k_upass<<<gE8, 512>>>(src_p, dst_p, src_s, dst_s, e0, e1);   // u2
    k_prep<<<gN, 512>>>(n, 1);                                   // S2, t=invdeg*u2
    k_upass<<<gE8, 512>>>(src_p, dst_p, src_s, dst_s, e0, e1);   // u3

    k_wcol<<<gW, 128>>>(feat_p, feat_s, n);

    k_match<<<1, 256>>>(W0, b0, W1, b1, W2, b2, Wr, br,
                        Wm1, bm1, Wm2, bm2, (float)n, (float*)d_out);
}